// round 10
// baseline (speedup 1.0000x reference)
#include <cuda_runtime.h>
#include <cuda_bf16.h>
#include <math.h>
#include <stdint.h>

#define BB 64
#define TT 512
#define DD 1024
#define HH 1024
#define VV 128
#define NCTA 128
#define NTHR 128
#define KC 64            // k elements per chunk
#define NCH 32           // chunks per phase (K = 2048)
#define PB 144           // bytes per staged row (64 bf16 + 8 pad)

// ---- dynamic smem layout (byte offsets) ----
#define ARR   9216           // one staged array: 64 rows * 144B
#define STAGE (4 * ARR)      // AH, AL, BH, BL = 36864B per stage
#define NSTG  4
#define AH0   0
#define AL0   ARR
#define BH0   (2 * ARR)
#define BL0   (3 * ARR)
#define SGATE (NSTG * STAGE)           // 147456: f32 [64][68]
#define SCST  (SGATE + 64 * 68 * 4)    // f32 [64][17]
#define STOKS (SCST + 64 * 17 * 4)     // 64 ints
#define SMEM_DYN (STOKS + 256 + 256)

// ---- persistent device scratch ----
__device__ __nv_bfloat16 g_WBh[2ull * 64 * 64 * 2048];  // permuted weights hi
__device__ __nv_bfloat16 g_WBl[2ull * 64 * 64 * 2048];  // permuted weights lo
__device__ __nv_bfloat16 g_embh[VV * DD];
__device__ __nv_bfloat16 g_embl[VV * DD];
__device__ __nv_bfloat16 g_h0h[2][BB][HH];
__device__ __nv_bfloat16 g_h0l[2][BB][HH];
__device__ __nv_bfloat16 g_h1h[2][BB][HH];
__device__ __nv_bfloat16 g_h1l[2][BB][HH];
__device__ float g_Hout[(size_t)BB * TT * HH];
__device__ volatile unsigned g_gen;
__device__ unsigned g_count;

__device__ __forceinline__ float sigf(float v) { return 1.0f / (1.0f + expf(-v)); }

__device__ __forceinline__ uint32_t smem_u32(const void* p) {
    uint32_t a;
    asm("{ .reg .u64 t; cvta.to.shared.u64 t, %1; cvt.u32.u64 %0, t; }" : "=r"(a) : "l"(p));
    return a;
}
__device__ __forceinline__ void cp16(uint32_t dst, const void* src) {
    asm volatile("cp.async.cg.shared.global [%0], [%1], 16;" :: "r"(dst), "l"(src));
}
__device__ __forceinline__ void cp_commit() { asm volatile("cp.async.commit_group;"); }
template<int N> __device__ __forceinline__ void cp_wait() {
    asm volatile("cp.async.wait_group %0;" :: "n"(N));
}
__device__ __forceinline__ uint32_t lds_u32(uint32_t a) {
    uint32_t v; asm volatile("ld.shared.b32 %0, [%1];" : "=r"(v) : "r"(a)); return v;
}
__device__ __forceinline__ float lds_f32(uint32_t a) {
    float v; asm volatile("ld.shared.f32 %0, [%1];" : "=f"(v) : "r"(a)); return v;
}
__device__ __forceinline__ void sts_u32(uint32_t a, uint32_t v) {
    asm volatile("st.shared.b32 [%0], %1;" :: "r"(a), "r"(v));
}
__device__ __forceinline__ void sts_f32(uint32_t a, float v) {
    asm volatile("st.shared.f32 [%0], %1;" :: "r"(a), "f"(v));
}
__device__ __forceinline__ void sts_v2(uint32_t a, float x, float y) {
    asm volatile("st.shared.v2.f32 [%0], {%1, %2};" :: "r"(a), "f"(x), "f"(y));
}
#define LDSM4(r0, r1, r2, r3, addr) \
    asm volatile("ldmatrix.sync.aligned.m8n8.x4.shared.b16 {%0,%1,%2,%3}, [%4];" \
                 : "=r"(r0), "=r"(r1), "=r"(r2), "=r"(r3) : "r"(addr))

__device__ __forceinline__ void mma_bf16(float* d,
    uint32_t a0, uint32_t a1, uint32_t a2, uint32_t a3, uint32_t b0, uint32_t b1) {
    asm volatile("mma.sync.aligned.m16n8k16.row.col.f32.bf16.bf16.f32 "
                 "{%0,%1,%2,%3}, {%4,%5,%6,%7}, {%8,%9}, {%0,%1,%2,%3};"
                 : "+f"(d[0]), "+f"(d[1]), "+f"(d[2]), "+f"(d[3])
                 : "r"(a0), "r"(a1), "r"(a2), "r"(a3), "r"(b0), "r"(b1));
}

__global__ void init_kernel() {
    int i = blockIdx.x * blockDim.x + threadIdx.x;
    if (i < 2 * BB * HH) {
        ((__nv_bfloat16*)g_h0h)[i] = __float2bfloat16(0.0f);
        ((__nv_bfloat16*)g_h0l)[i] = __float2bfloat16(0.0f);
        ((__nv_bfloat16*)g_h1h)[i] = __float2bfloat16(0.0f);
        ((__nv_bfloat16*)g_h1l)[i] = __float2bfloat16(0.0f);
    }
    if (i == 0) { g_count = 0; g_gen = 0; }
}

// weight preconvert: permuted [u][tile][n][k], n = gate*16+j, k over [Wx|Wh]
__global__ void convert_weights_kernel(const float* __restrict__ Wx,
                                       const float* __restrict__ Wh) {
    size_t idx = (size_t)blockIdx.x * blockDim.x + threadIdx.x;
    if (idx >= 2ull * 64 * 64 * 2048) return;
    int k    = idx & 2047;
    int n    = (idx >> 11) & 63;
    int tile = (idx >> 17) & 63;
    int u    = (int)(idx >> 23);
    int gate = n >> 4, j = n & 15;
    int r = gate * 1024 + tile * 16 + j;
    float w = (k < 1024) ? Wx[((size_t)u * 4096 + r) * 1024 + k]
                         : Wh[((size_t)u * 4096 + r) * 1024 + (k - 1024)];
    __nv_bfloat16 hi = __float2bfloat16(w);
    __nv_bfloat16 lo = __float2bfloat16(w - __bfloat162float(hi));
    g_WBh[idx] = hi;
    g_WBl[idx] = lo;
}

__global__ void convert_embed_kernel(const float* __restrict__ embed) {
    int i = blockIdx.x * blockDim.x + threadIdx.x;
    if (i >= VV * DD) return;
    float w = embed[i];
    __nv_bfloat16 hi = __float2bfloat16(w);
    __nv_bfloat16 lo = __float2bfloat16(w - __bfloat162float(hi));
    g_embh[i] = hi;
    g_embl[i] = lo;
}

__device__ __forceinline__ void grid_barrier() {
    __syncthreads();
    if (threadIdx.x == 0) {
        unsigned gen = g_gen;
        __threadfence();
        if (atomicAdd(&g_count, 1u) == NCTA - 1) {
            g_count = 0;
            __threadfence();
            g_gen = gen + 1;
        } else {
            while (g_gen == gen) { __nanosleep(32); }
            __threadfence();
        }
    }
    __syncthreads();
}

// Persistent bf16-split mma.sync LSTM, 4-stage pipelined, m32n32 warp tiles.
// 128 CTAs x 128 thr (4 warps). CTA: layer u = blockIdx>>6, tile = blockIdx&63.
// Warp grid 2x2 over the 64x64 (batch x gate-col) tile; warp tile = 32x32.
__global__ __launch_bounds__(NTHR, 1) void lstm_persistent_kernel(
    const int* __restrict__ x, const float* __restrict__ bias)
{
    extern __shared__ char sm_raw[];
    const uint32_t sb = smem_u32(sm_raw);

    const int tid  = threadIdx.x;
    const int wid  = tid >> 5;
    const int lane = tid & 31;
    const int u    = blockIdx.x >> 6;
    const int tile = blockIdx.x & 63;
    const int col0 = tile * 16;

    // warp tile m32 x n32
    const int m0 = (wid & 1) * 32;
    const int n0 = (wid >> 1) * 32;
    const int lg = lane >> 2;
    const int t2 = (lane & 3) * 2;

    // ldmatrix lane addresses (byte offsets within a staged array), lower m16/n16;
    // the upper half is +16*PB.
    const uint32_t a_lrow = (uint32_t)(m0 + (lane & 7) + ((lane >> 3) & 1) * 8) * PB
                          + ((lane >> 4) & 1) * 16;
    const uint32_t b_lrow = (uint32_t)(n0 + (lane & 7) + ((lane >> 4) & 1) * 8) * PB
                          + ((lane >> 3) & 1) * 16;

    // staging role: warp q stages array q (0 AH, 1 AL, 2 BH, 3 BL); 16 cp16/thread
    const int q = wid;

    // pointwise role
    const int pj  = tid & 15;
    const int pb0 = tid >> 4;   // 0..7
    const float* bL = bias + u * 4096;
    const float bi_ = bL[0    + col0 + pj];
    const float bf_ = bL[1024 + col0 + pj];
    const float bg_ = bL[2048 + col0 + pj];
    const float bo_ = bL[3072 + col0 + pj];

    for (int i = tid; i < 64 * 17; i += NTHR) sts_f32(sb + SCST + i * 4, 0.0f);
    __syncthreads();

    const __nv_bfloat16* wbh = g_WBh + ((size_t)(u * 64 + tile) * 64) * 2048;
    const __nv_bfloat16* wbl = g_WBl + ((size_t)(u * 64 + tile) * 64) * 2048;
    const __nv_bfloat16* wsel = (q == 2) ? wbh : wbl;   // used when q >= 2

    for (int p = 0; p <= TT; p++) {
        const bool valid = (u == 0) ? (p < TT) : (p >= 1);
        const int  tc    = (u == 0) ? (valid ? p : TT - 1) : (valid ? p - 1 : 0);
        const int  wbuf  = tc & 1;
        const int  rbuf  = (tc + 1) & 1;

        if (tid < BB) sts_u32(sb + STOKS + tid * 4, (uint32_t)x[tid * TT + tc]);
        __syncthreads();

        float acc[2][4][4];
#pragma unroll
        for (int a = 0; a < 2; a++)
#pragma unroll
            for (int b = 0; b < 4; b++)
#pragma unroll
                for (int e = 0; e < 4; e++) acc[a][b][e] = 0.0f;

        // stage chunk c (k in [c*64, c*64+64)) into ring buffer c&3; warp q owns array q
        auto stage_chunk = [&](int c) {
            const uint32_t dstbase = sb + (c & 3) * STAGE + q * ARR;
#pragma unroll
            for (int i = 0; i < 16; i++) {
                const int idx = lane + 32 * i;
                const int row = idx >> 3;
                const int f4  = idx & 7;
                const uint32_t dst = dstbase + (uint32_t)row * PB + f4 * 16;
                const __nv_bfloat16* src;
                if (q >= 2) {
                    src = wsel + (size_t)row * 2048 + c * KC + f4 * 8;
                } else {
                    if (u == 0) {
                        if (c < 16) {
                            int tok = (int)lds_u32(sb + STOKS + row * 4);
                            src = ((q == 0) ? g_embh : g_embl) + (size_t)tok * DD + c * KC + f4 * 8;
                        } else {
                            src = ((q == 0) ? g_h0h[rbuf][row] : g_h0l[rbuf][row]) + (c - 16) * KC + f4 * 8;
                        }
                    } else {
                        if (c < 16) src = ((q == 0) ? g_h0h[wbuf][row] : g_h0l[wbuf][row]) + c * KC + f4 * 8;
                        else        src = ((q == 0) ? g_h1h[rbuf][row] : g_h1l[rbuf][row]) + (c - 16) * KC + f4 * 8;
                    }
                }
                cp16(dst, src);
            }
            cp_commit();
        };

        // prologue: 3 chunks in flight
        stage_chunk(0); stage_chunk(1); stage_chunk(2);

        for (int c = 0; c < NCH; c++) {
            if (c < NCH - 2)       cp_wait<2>();
            else if (c == NCH - 2) cp_wait<1>();
            else                   cp_wait<0>();
            __syncthreads();                     // chunk c visible; compute(c-1) done
            if (c + 3 < NCH) stage_chunk(c + 3); // overwrites buffer (c-1)&3 — safe

            const uint32_t base = sb + (c & 3) * STAGE;
            const uint32_t aH  = base + AH0 + a_lrow;
            const uint32_t aL  = base + AL0 + a_lrow;
            const uint32_t bH  = base + BH0 + b_lrow;
            const uint32_t bLo = base + BL0 + b_lrow;
#pragma unroll
            for (int ks = 0; ks < 4; ks++) {
                const uint32_t ko = ks * 32;
                uint32_t ah[8], al[8], bh[8], bl[8];
                LDSM4(ah[0], ah[1], ah[2], ah[3], aH + ko);
                LDSM4(ah[4], ah[5], ah[6], ah[7], aH + ko + 16 * PB);
                LDSM4(bh[0], bh[1], bh[2], bh[3], bH + ko);
                LDSM4(bh[4], bh[5], bh[6], bh[7], bH + ko + 16 * PB);
                LDSM4(al[0], al[1], al[2], al[3], aL + ko);
                LDSM4(al[4], al[5], al[6], al[7], aL + ko + 16 * PB);
                LDSM4(bl[0], bl[1], bl[2], bl[3], bLo + ko);
                LDSM4(bl[4], bl[5], bl[6], bl[7], bLo + ko + 16 * PB);
#pragma unroll
                for (int mi = 0; mi < 2; mi++) {
                    const uint32_t* A  = ah + mi * 4;
                    const uint32_t* AL2 = al + mi * 4;
#pragma unroll
                    for (int ni = 0; ni < 4; ni++) {
                        mma_bf16(acc[mi][ni], A[0], A[1], A[2], A[3], bh[2 * ni], bh[2 * ni + 1]);
                        mma_bf16(acc[mi][ni], A[0], A[1], A[2], A[3], bl[2 * ni], bl[2 * ni + 1]);
                        mma_bf16(acc[mi][ni], AL2[0], AL2[1], AL2[2], AL2[3], bh[2 * ni], bh[2 * ni + 1]);
                    }
                }
            }
        }
        __syncthreads();

        // D frags -> gate smem [64 m][68 f32 pitch]
#pragma unroll
        for (int mi = 0; mi < 2; mi++) {
            const uint32_t grow = sb + SGATE + (uint32_t)(m0 + mi * 16 + lg) * 272
                                + (uint32_t)(n0 + t2) * 4;
#pragma unroll
            for (int ni = 0; ni < 4; ni++) {
                sts_v2(grow + ni * 32,           acc[mi][ni][0], acc[mi][ni][1]);
                sts_v2(grow + ni * 32 + 8 * 272, acc[mi][ni][2], acc[mi][ni][3]);
            }
        }
        __syncthreads();

        // pointwise: thread owns col j = pj, batches pb0 + 8*qq
        if (valid) {
#pragma unroll
            for (int qq = 0; qq < 8; qq++) {
                const int b   = pb0 + 8 * qq;
                const int col = col0 + pj;
                const uint32_t gaddr = sb + SGATE + b * 272;
                float gi = lds_f32(gaddr + (0  + pj) * 4) + bi_;
                float gf = lds_f32(gaddr + (16 + pj) * 4) + bf_;
                float gg = lds_f32(gaddr + (32 + pj) * 4) + bg_;
                float go = lds_f32(gaddr + (48 + pj) * 4) + bo_;
                const uint32_t caddr = sb + SCST + (b * 17 + pj) * 4;
                float c_old = lds_f32(caddr);
                float c_new = sigf(gf) * c_old + sigf(gi) * tanhf(gg);
                float h_new = sigf(go) * tanhf(c_new);
                sts_f32(caddr, c_new);
                __nv_bfloat16 hh = __float2bfloat16(h_new);
                __nv_bfloat16 hl = __float2bfloat16(h_new - __bfloat162float(hh));
                if (u == 0) {
                    g_h0h[wbuf][b][col] = hh;
                    g_h0l[wbuf][b][col] = hl;
                } else {
                    g_h1h[wbuf][b][col] = hh;
                    g_h1l[wbuf][b][col] = hl;
                    g_Hout[((size_t)b * TT + tc) * HH + col] = h_new;
                }
            }
        }
        grid_barrier();
    }
}

// logits[m, v] = g_Hout[m, :] . Wout[v, :] + bout[v]  (M=32768, N=128, K=1024)
__global__ __launch_bounds__(128) void out_proj_kernel(
    const float* __restrict__ Wout, const float* __restrict__ bout,
    float* __restrict__ out)
{
    __shared__ float As[32][68];
    __shared__ float Ws[32][36];

    const int tid = threadIdx.x;
    const int m0  = blockIdx.x * 64;
    const int v0  = blockIdx.y * 32;
    const int tm  = tid & 15;
    const int tn  = tid >> 4;

    float acc[4][4];
#pragma unroll
    for (int i = 0; i < 4; i++)
#pragma unroll
        for (int j = 0; j < 4; j++) acc[i][j] = 0.0f;

#pragma unroll 1
    for (int k0 = 0; k0 < HH; k0 += 32) {
#pragma unroll
        for (int qy = 0; qy < 4; qy++) {
            int idx = tid + 128 * qy;
            int bb = idx >> 3, kv = idx & 7, k = k0 + kv * 4;
            float4 v = *reinterpret_cast<const float4*>(&g_Hout[(size_t)(m0 + bb) * HH + k]);
            int kr = kv * 4;
            As[kr + 0][bb] = v.x; As[kr + 1][bb] = v.y;
            As[kr + 2][bb] = v.z; As[kr + 3][bb] = v.w;
        }
#pragma unroll
        for (int qy = 0; qy < 2; qy++) {
            int idx = tid + 128 * qy;
            int n = idx >> 3, kv = idx & 7, k = k0 + kv * 4;
            float4 v = *reinterpret_cast<const float4*>(&Wout[(size_t)(v0 + n) * HH + k]);
            int kr = kv * 4;
            Ws[kr + 0][n] = v.x; Ws[kr + 1][n] = v.y;
            Ws[kr + 2][n] = v.z; Ws[kr + 3][n] = v.w;
        }
        __syncthreads();
#pragma unroll
        for (int kk = 0; kk < 32; kk++) {
            float4 a = *reinterpret_cast<const float4*>(&As[kk][tm << 2]);
            float4 w = *reinterpret_cast<const float4*>(&Ws[kk][tn << 2]);
            float av[4] = {a.x, a.y, a.z, a.w};
            float wv[4] = {w.x, w.y, w.z, w.w};
#pragma unroll
            for (int i = 0; i < 4; i++)
#pragma unroll
                for (int j = 0; j < 4; j++)
                    acc[i][j] = fmaf(av[i], wv[j], acc[i][j]);
        }
        __syncthreads();
    }

#pragma unroll
    for (int i = 0; i < 4; i++) {
        int m = m0 + (tm << 2) + i;
#pragma unroll
        for (int j = 0; j < 4; j++) {
            int v = v0 + (tn << 2) + j;
            out[(size_t)m * VV + v] = acc[i][j] + bout[v];
        }
    }
}

extern "C" void kernel_launch(void* const* d_in, const int* in_sizes, int n_in,
                              void* d_out, int out_size)
{
    const int*   x     = (const int*)d_in[0];
    const float* embed = (const float*)d_in[1];
    const float* Wx    = (const float*)d_in[2];
    const float* Wh    = (const float*)d_in[3];
    const float* bias  = (const float*)d_in[4];
    const float* Wout  = (const float*)d_in[5];
    const float* bout  = (const float*)d_in[6];
    float*       out   = (float*)d_out;

    static int smem_set = 0;
    if (!smem_set) {
        cudaFuncSetAttribute(lstm_persistent_kernel,
                             cudaFuncAttributeMaxDynamicSharedMemorySize, SMEM_DYN);
        smem_set = 1;
    }

    init_kernel<<<(2 * BB * HH + 255) / 256, 256>>>();
    convert_weights_kernel<<<(int)((2ull * 64 * 64 * 2048 + 255) / 256), 256>>>(Wx, Wh);
    convert_embed_kernel<<<(VV * DD + 255) / 256, 256>>>(embed);
    lstm_persistent_kernel<<<NCTA, NTHR, SMEM_DYN>>>(x, bias);
    out_proj_kernel<<<dim3(BB * TT / 64, VV / 32), 128>>>(Wout, bout, out);
}

// round 11
// speedup vs baseline: 1.7189x; 1.7189x over previous
#include <cuda_runtime.h>
#include <cuda_bf16.h>
#include <math.h>
#include <stdint.h>

#define BB 64
#define TT 512
#define DD 1024
#define HH 1024
#define VV 128
#define NCTA 128
#define NTHR 256
#define KC 64            // k elements per chunk
#define NCH 32           // chunks per phase (K = 2048)
#define PB 144           // bytes per staged row (64 bf16 + 8 pad)

// ---- dynamic smem layout (byte offsets) ----
#define ARR   9216           // one staged array: 64 rows * 144B
#define STAGE (4 * ARR)      // AH, AL, BH, BL = 36864B per stage
#define NSTG  4
#define AH0   0
#define AL0   ARR
#define BH0   (2 * ARR)
#define BL0   (3 * ARR)
#define SGATE (NSTG * STAGE)           // 147456: f32 [64][68]
#define SCST  (SGATE + 64 * 68 * 4)    // f32 [64][17]
#define STOKS (SCST + 64 * 17 * 4)     // 64 ints
#define SMEM_DYN (STOKS + 256 + 256)

// ---- persistent device scratch ----
__device__ __nv_bfloat16 g_WBh[2ull * 64 * 64 * 2048];  // permuted weights hi
__device__ __nv_bfloat16 g_WBl[2ull * 64 * 64 * 2048];  // permuted weights lo
__device__ __nv_bfloat16 g_embh[VV * DD];
__device__ __nv_bfloat16 g_embl[VV * DD];
__device__ __nv_bfloat16 g_h0h[2][BB][HH];
__device__ __nv_bfloat16 g_h0l[2][BB][HH];
__device__ __nv_bfloat16 g_h1h[2][BB][HH];
__device__ __nv_bfloat16 g_h1l[2][BB][HH];
__device__ float g_Hout[(size_t)BB * TT * HH];
__device__ volatile unsigned g_gen;
__device__ unsigned g_count;

__device__ __forceinline__ float sigf(float v) { return 1.0f / (1.0f + expf(-v)); }

__device__ __forceinline__ uint32_t smem_u32(const void* p) {
    uint32_t a;
    asm("{ .reg .u64 t; cvta.to.shared.u64 t, %1; cvt.u32.u64 %0, t; }" : "=r"(a) : "l"(p));
    return a;
}
__device__ __forceinline__ void cp16(uint32_t dst, const void* src) {
    asm volatile("cp.async.cg.shared.global [%0], [%1], 16;" :: "r"(dst), "l"(src));
}
__device__ __forceinline__ void cp_commit() { asm volatile("cp.async.commit_group;"); }
template<int N> __device__ __forceinline__ void cp_wait() {
    asm volatile("cp.async.wait_group %0;" :: "n"(N));
}
__device__ __forceinline__ uint32_t lds_u32(uint32_t a) {
    uint32_t v; asm volatile("ld.shared.b32 %0, [%1];" : "=r"(v) : "r"(a)); return v;
}
__device__ __forceinline__ float lds_f32(uint32_t a) {
    float v; asm volatile("ld.shared.f32 %0, [%1];" : "=f"(v) : "r"(a)); return v;
}
__device__ __forceinline__ void sts_u32(uint32_t a, uint32_t v) {
    asm volatile("st.shared.b32 [%0], %1;" :: "r"(a), "r"(v));
}
__device__ __forceinline__ void sts_f32(uint32_t a, float v) {
    asm volatile("st.shared.f32 [%0], %1;" :: "r"(a), "f"(v));
}
__device__ __forceinline__ void sts_v2(uint32_t a, float x, float y) {
    asm volatile("st.shared.v2.f32 [%0], {%1, %2};" :: "r"(a), "f"(x), "f"(y));
}
#define LDSM4(r0, r1, r2, r3, addr) \
    asm volatile("ldmatrix.sync.aligned.m8n8.x4.shared.b16 {%0,%1,%2,%3}, [%4];" \
                 : "=r"(r0), "=r"(r1), "=r"(r2), "=r"(r3) : "r"(addr))

__device__ __forceinline__ void mma_bf16(float* d,
    uint32_t a0, uint32_t a1, uint32_t a2, uint32_t a3, uint32_t b0, uint32_t b1) {
    asm volatile("mma.sync.aligned.m16n8k16.row.col.f32.bf16.bf16.f32 "
                 "{%0,%1,%2,%3}, {%4,%5,%6,%7}, {%8,%9}, {%0,%1,%2,%3};"
                 : "+f"(d[0]), "+f"(d[1]), "+f"(d[2]), "+f"(d[3])
                 : "r"(a0), "r"(a1), "r"(a2), "r"(a3), "r"(b0), "r"(b1));
}

__global__ void init_kernel() {
    int i = blockIdx.x * blockDim.x + threadIdx.x;
    if (i < 2 * BB * HH) {
        ((__nv_bfloat16*)g_h0h)[i] = __float2bfloat16(0.0f);
        ((__nv_bfloat16*)g_h0l)[i] = __float2bfloat16(0.0f);
        ((__nv_bfloat16*)g_h1h)[i] = __float2bfloat16(0.0f);
        ((__nv_bfloat16*)g_h1l)[i] = __float2bfloat16(0.0f);
    }
    if (i == 0) { g_count = 0; g_gen = 0; }
}

// weight preconvert: permuted [u][tile][n][k], n = gate*16+j, k over [Wx|Wh]
__global__ void convert_weights_kernel(const float* __restrict__ Wx,
                                       const float* __restrict__ Wh) {
    size_t idx = (size_t)blockIdx.x * blockDim.x + threadIdx.x;
    if (idx >= 2ull * 64 * 64 * 2048) return;
    int k    = idx & 2047;
    int n    = (idx >> 11) & 63;
    int tile = (idx >> 17) & 63;
    int u    = (int)(idx >> 23);
    int gate = n >> 4, j = n & 15;
    int r = gate * 1024 + tile * 16 + j;
    float w = (k < 1024) ? Wx[((size_t)u * 4096 + r) * 1024 + k]
                         : Wh[((size_t)u * 4096 + r) * 1024 + (k - 1024)];
    __nv_bfloat16 hi = __float2bfloat16(w);
    __nv_bfloat16 lo = __float2bfloat16(w - __bfloat162float(hi));
    g_WBh[idx] = hi;
    g_WBl[idx] = lo;
}

__global__ void convert_embed_kernel(const float* __restrict__ embed) {
    int i = blockIdx.x * blockDim.x + threadIdx.x;
    if (i >= VV * DD) return;
    float w = embed[i];
    __nv_bfloat16 hi = __float2bfloat16(w);
    __nv_bfloat16 lo = __float2bfloat16(w - __bfloat162float(hi));
    g_embh[i] = hi;
    g_embl[i] = lo;
}

__device__ __forceinline__ void grid_barrier() {
    __syncthreads();
    if (threadIdx.x == 0) {
        unsigned gen = g_gen;
        __threadfence();
        if (atomicAdd(&g_count, 1u) == NCTA - 1) {
            g_count = 0;
            __threadfence();
            g_gen = gen + 1;
        } else {
            while (g_gen == gen) { __nanosleep(32); }
            __threadfence();
        }
    }
    __syncthreads();
}

// Persistent bf16-split mma.sync LSTM, 4-stage pipelined, m32n16 warp tiles.
// 128 CTAs x 256 thr (8 warps). CTA: layer u = blockIdx>>6, tile = blockIdx&63.
// Warp grid 2(m) x 4(n) over the 64x64 (batch x gate-col) tile; warp tile = 32x16.
__global__ __launch_bounds__(NTHR, 1) void lstm_persistent_kernel(
    const int* __restrict__ x, const float* __restrict__ bias)
{
    extern __shared__ char sm_raw[];
    const uint32_t sb = smem_u32(sm_raw);

    const int tid  = threadIdx.x;
    const int wid  = tid >> 5;
    const int lane = tid & 31;
    const int u    = blockIdx.x >> 6;
    const int tile = blockIdx.x & 63;
    const int col0 = tile * 16;

    // warp tile m32 x n16
    const int m0 = (wid & 1) * 32;
    const int n0 = (wid >> 1) * 16;
    const int lg = lane >> 2;
    const int t2 = (lane & 3) * 2;

    // ldmatrix lane addresses (byte offsets within a staged array);
    // A covers m0..m0+15, the upper m16 is +16*PB.
    const uint32_t a_lrow = (uint32_t)(m0 + (lane & 7) + ((lane >> 3) & 1) * 8) * PB
                          + ((lane >> 4) & 1) * 16;
    const uint32_t b_lrow = (uint32_t)(n0 + (lane & 7) + ((lane >> 4) & 1) * 8) * PB
                          + ((lane >> 3) & 1) * 16;

    // staging role: q = array (0 AH, 1 AL, 2 BH, 3 BL); 64 threads per array,
    // thread covers f4 = rr&7 at rows (rr>>3) + 8*i, i<8
    const int q  = tid >> 6;
    const int rr = tid & 63;

    // pointwise role
    const int pj  = tid & 15;
    const int pb0 = tid >> 4;   // 0..15
    const float* bL = bias + u * 4096;
    const float bi_ = bL[0    + col0 + pj];
    const float bf_ = bL[1024 + col0 + pj];
    const float bg_ = bL[2048 + col0 + pj];
    const float bo_ = bL[3072 + col0 + pj];

    for (int i = tid; i < 64 * 17; i += NTHR) sts_f32(sb + SCST + i * 4, 0.0f);
    __syncthreads();

    const __nv_bfloat16* wbh = g_WBh + ((size_t)(u * 64 + tile) * 64) * 2048;
    const __nv_bfloat16* wbl = g_WBl + ((size_t)(u * 64 + tile) * 64) * 2048;
    const __nv_bfloat16* wsel = (q == 2) ? wbh : wbl;   // used when q >= 2

    for (int p = 0; p <= TT; p++) {
        const bool valid = (u == 0) ? (p < TT) : (p >= 1);
        const int  tc    = (u == 0) ? (valid ? p : TT - 1) : (valid ? p - 1 : 0);
        const int  wbuf  = tc & 1;
        const int  rbuf  = (tc + 1) & 1;

        if (tid < BB) sts_u32(sb + STOKS + tid * 4, (uint32_t)x[tid * TT + tc]);
        __syncthreads();

        float acc[2][2][4];
#pragma unroll
        for (int a = 0; a < 2; a++)
#pragma unroll
            for (int b = 0; b < 2; b++)
#pragma unroll
                for (int e = 0; e < 4; e++) acc[a][b][e] = 0.0f;

        // stage chunk c (k in [c*64, c*64+64)) into ring buffer c&3
        auto stage_chunk = [&](int c) {
            const uint32_t dstb = sb + (c & 3) * STAGE + q * ARR + (rr & 7) * 16;
#pragma unroll
            for (int i = 0; i < 8; i++) {
                const int row = (rr >> 3) + 8 * i;
                const int f4  = rr & 7;
                const uint32_t dst = dstb + (uint32_t)row * PB;
                const __nv_bfloat16* src;
                if (q >= 2) {
                    src = wsel + (size_t)row * 2048 + c * KC + f4 * 8;
                } else {
                    if (u == 0) {
                        if (c < 16) {
                            int tok = (int)lds_u32(sb + STOKS + row * 4);
                            src = ((q == 0) ? g_embh : g_embl) + (size_t)tok * DD + c * KC + f4 * 8;
                        } else {
                            src = ((q == 0) ? g_h0h[rbuf][row] : g_h0l[rbuf][row]) + (c - 16) * KC + f4 * 8;
                        }
                    } else {
                        if (c < 16) src = ((q == 0) ? g_h0h[wbuf][row] : g_h0l[wbuf][row]) + c * KC + f4 * 8;
                        else        src = ((q == 0) ? g_h1h[rbuf][row] : g_h1l[rbuf][row]) + (c - 16) * KC + f4 * 8;
                    }
                }
                cp16(dst, src);
            }
            cp_commit();
        };

        // prologue: 3 chunks in flight
        stage_chunk(0); stage_chunk(1); stage_chunk(2);

        for (int c = 0; c < NCH; c++) {
            if (c < NCH - 2)       cp_wait<2>();
            else if (c == NCH - 2) cp_wait<1>();
            else                   cp_wait<0>();
            __syncthreads();                     // chunk c visible; compute(c-1) done
            if (c + 3 < NCH) stage_chunk(c + 3); // overwrites buffer (c-1)&3 — safe

            const uint32_t base = sb + (c & 3) * STAGE;
            const uint32_t aH  = base + AH0 + a_lrow;
            const uint32_t aL  = base + AL0 + a_lrow;
            const uint32_t bH  = base + BH0 + b_lrow;
            const uint32_t bLo = base + BL0 + b_lrow;
#pragma unroll
            for (int ks = 0; ks < 4; ks++) {
                const uint32_t ko = ks * 32;
                uint32_t ah[8], al[8], bh[4], bl[4];
                LDSM4(ah[0], ah[1], ah[2], ah[3], aH + ko);
                LDSM4(ah[4], ah[5], ah[6], ah[7], aH + ko + 16 * PB);
                LDSM4(bh[0], bh[1], bh[2], bh[3], bH + ko);
                LDSM4(al[0], al[1], al[2], al[3], aL + ko);
                LDSM4(al[4], al[5], al[6], al[7], aL + ko + 16 * PB);
                LDSM4(bl[0], bl[1], bl[2], bl[3], bLo + ko);
#pragma unroll
                for (int mi = 0; mi < 2; mi++) {
                    const uint32_t* A   = ah + mi * 4;
                    const uint32_t* AL2 = al + mi * 4;
#pragma unroll
                    for (int ni = 0; ni < 2; ni++) {
                        mma_bf16(acc[mi][ni], A[0], A[1], A[2], A[3], bh[2 * ni], bh[2 * ni + 1]);
                        mma_bf16(acc[mi][ni], A[0], A[1], A[2], A[3], bl[2 * ni], bl[2 * ni + 1]);
                        mma_bf16(acc[mi][ni], AL2[0], AL2[1], AL2[2], AL2[3], bh[2 * ni], bh[2 * ni + 1]);
                    }
                }
            }
        }
        __syncthreads();

        // D frags -> gate smem [64 m][68 f32 pitch]
#pragma unroll
        for (int mi = 0; mi < 2; mi++) {
            const uint32_t grow = sb + SGATE + (uint32_t)(m0 + mi * 16 + lg) * 272
                                + (uint32_t)(n0 + t2) * 4;
#pragma unroll
            for (int ni = 0; ni < 2; ni++) {
                sts_v2(grow + ni * 32,           acc[mi][ni][0], acc[mi][ni][1]);
                sts_v2(grow + ni * 32 + 8 * 272, acc[mi][ni][2], acc[mi][ni][3]);
            }
        }
        __syncthreads();

        // pointwise: thread owns col j = pj, batches pb0 + 16*qq
        if (valid) {
#pragma unroll
            for (int qq = 0; qq < 4; qq++) {
                const int b   = pb0 + 16 * qq;
                const int col = col0 + pj;
                const uint32_t gaddr = sb + SGATE + b * 272;
                float gi = lds_f32(gaddr + (0  + pj) * 4) + bi_;
                float gf = lds_f32(gaddr + (16 + pj) * 4) + bf_;
                float gg = lds_f32(gaddr + (32 + pj) * 4) + bg_;
                float go = lds_f32(gaddr + (48 + pj) * 4) + bo_;
                const uint32_t caddr = sb + SCST + (b * 17 + pj) * 4;
                float c_old = lds_f32(caddr);
                float c_new = sigf(gf) * c_old + sigf(gi) * tanhf(gg);
                float h_new = sigf(go) * tanhf(c_new);
                sts_f32(caddr, c_new);
                __nv_bfloat16 hh = __float2bfloat16(h_new);
                __nv_bfloat16 hl = __float2bfloat16(h_new - __bfloat162float(hh));
                if (u == 0) {
                    g_h0h[wbuf][b][col] = hh;
                    g_h0l[wbuf][b][col] = hl;
                } else {
                    g_h1h[wbuf][b][col] = hh;
                    g_h1l[wbuf][b][col] = hl;
                    g_Hout[((size_t)b * TT + tc) * HH + col] = h_new;
                }
            }
        }
        grid_barrier();
    }
}

// logits[m, v] = g_Hout[m, :] . Wout[v, :] + bout[v]  (M=32768, N=128, K=1024)
__global__ __launch_bounds__(128) void out_proj_kernel(
    const float* __restrict__ Wout, const float* __restrict__ bout,
    float* __restrict__ out)
{
    __shared__ float As[32][68];
    __shared__ float Ws[32][36];

    const int tid = threadIdx.x;
    const int m0  = blockIdx.x * 64;
    const int v0  = blockIdx.y * 32;
    const int tm  = tid & 15;
    const int tn  = tid >> 4;

    float acc[4][4];
#pragma unroll
    for (int i = 0; i < 4; i++)
#pragma unroll
        for (int j = 0; j < 4; j++) acc[i][j] = 0.0f;

#pragma unroll 1
    for (int k0 = 0; k0 < HH; k0 += 32) {
#pragma unroll
        for (int qy = 0; qy < 4; qy++) {
            int idx = tid + 128 * qy;
            int bb = idx >> 3, kv = idx & 7, k = k0 + kv * 4;
            float4 v = *reinterpret_cast<const float4*>(&g_Hout[(size_t)(m0 + bb) * HH + k]);
            int kr = kv * 4;
            As[kr + 0][bb] = v.x; As[kr + 1][bb] = v.y;
            As[kr + 2][bb] = v.z; As[kr + 3][bb] = v.w;
        }
#pragma unroll
        for (int qy = 0; qy < 2; qy++) {
            int idx = tid + 128 * qy;
            int n = idx >> 3, kv = idx & 7, k = k0 + kv * 4;
            float4 v = *reinterpret_cast<const float4*>(&Wout[(size_t)(v0 + n) * HH + k]);
            int kr = kv * 4;
            Ws[kr + 0][n] = v.x; Ws[kr + 1][n] = v.y;
            Ws[kr + 2][n] = v.z; Ws[kr + 3][n] = v.w;
        }
        __syncthreads();
#pragma unroll
        for (int kk = 0; kk < 32; kk++) {
            float4 a = *reinterpret_cast<const float4*>(&As[kk][tm << 2]);
            float4 w = *reinterpret_cast<const float4*>(&Ws[kk][tn << 2]);
            float av[4] = {a.x, a.y, a.z, a.w};
            float wv[4] = {w.x, w.y, w.z, w.w};
#pragma unroll
            for (int i = 0; i < 4; i++)
#pragma unroll
                for (int j = 0; j < 4; j++)
                    acc[i][j] = fmaf(av[i], wv[j], acc[i][j]);
        }
        __syncthreads();
    }

#pragma unroll
    for (int i = 0; i < 4; i++) {
        int m = m0 + (tm << 2) + i;
#pragma unroll
        for (int j = 0; j < 4; j++) {
            int v = v0 + (tn << 2) + j;
            out[(size_t)m * VV + v] = acc[i][j] + bout[v];
        }
    }
}

extern "C" void kernel_launch(void* const* d_in, const int* in_sizes, int n_in,
                              void* d_out, int out_size)
{
    const int*   x     = (const int*)d_in[0];
    const float* embed = (const float*)d_in[1];
    const float* Wx    = (const float*)d_in[2];
    const float* Wh    = (const float*)d_in[3];
    const float* bias  = (const float*)d_in[4];
    const float* Wout  = (const float*)d_in[5];
    const float* bout  = (const float*)d_in[6];
    float*       out   = (float*)d_out;

    static int smem_set = 0;
    if (!smem_set) {
        cudaFuncSetAttribute(lstm_persistent_kernel,
                             cudaFuncAttributeMaxDynamicSharedMemorySize, SMEM_DYN);
        smem_set = 1;
    }

    init_kernel<<<(2 * BB * HH + 255) / 256, 256>>>();
    convert_weights_kernel<<<(int)((2ull * 64 * 64 * 2048 + 255) / 256), 256>>>(Wx, Wh);
    convert_embed_kernel<<<(VV * DD + 255) / 256, 256>>>(embed);
    lstm_persistent_kernel<<<NCTA, NTHR, SMEM_DYN>>>(x, bias);
    out_proj_kernel<<<dim3(BB * TT / 64, VV / 32), 128>>>(Wout, bout, out);
}

// round 12
// speedup vs baseline: 1.8476x; 1.0749x over previous
#include <cuda_runtime.h>
#include <cuda_bf16.h>
#include <math.h>
#include <stdint.h>

#define BB 64
#define TT 512
#define DD 1024
#define HH 1024
#define VV 128
#define NCTA 128
#define NTHR 512
#define KC 64            // k elements per chunk
#define NCH 32           // chunks per phase (K = 2048)
#define NPAIR 16         // chunk pairs per phase
#define PB 144           // bytes per staged row (64 bf16 + 8 pad)

// ---- dynamic smem layout (byte offsets) ----
#define ARR    9216          // one staged array: 64 rows * 144B
#define CHUNK  (4 * ARR)     // AH, AL, BH, BL = 36864B per chunk
#define SLOT   (2 * CHUNK)   // a ring slot holds one chunk PAIR = 73728B
#define NSLOT  3
#define SGATE  0                         // f32 [64][68]  (aliases slot 0; safe)
#define SCST   (NSLOT * SLOT)            // 221184: f32 [64][17] persistent
#define STOKS  (SCST + 64 * 17 * 4)      // 64 ints
#define SMEM_DYN (STOKS + 256 + 256)

// ---- persistent device scratch ----
__device__ __nv_bfloat16 g_WBh[2ull * 64 * 64 * 2048];  // permuted weights hi
__device__ __nv_bfloat16 g_WBl[2ull * 64 * 64 * 2048];  // permuted weights lo
__device__ __nv_bfloat16 g_embh[VV * DD];
__device__ __nv_bfloat16 g_embl[VV * DD];
__device__ __nv_bfloat16 g_h0h[2][BB][HH];
__device__ __nv_bfloat16 g_h0l[2][BB][HH];
__device__ __nv_bfloat16 g_h1h[2][BB][HH];
__device__ __nv_bfloat16 g_h1l[2][BB][HH];
__device__ float g_Hout[(size_t)BB * TT * HH];
__device__ volatile unsigned g_gen;
__device__ unsigned g_count;

__device__ __forceinline__ float sigf(float v) { return 1.0f / (1.0f + expf(-v)); }

__device__ __forceinline__ uint32_t smem_u32(const void* p) {
    uint32_t a;
    asm("{ .reg .u64 t; cvta.to.shared.u64 t, %1; cvt.u32.u64 %0, t; }" : "=r"(a) : "l"(p));
    return a;
}
__device__ __forceinline__ void cp16(uint32_t dst, const void* src) {
    asm volatile("cp.async.cg.shared.global [%0], [%1], 16;" :: "r"(dst), "l"(src));
}
__device__ __forceinline__ void cp_commit() { asm volatile("cp.async.commit_group;"); }
template<int N> __device__ __forceinline__ void cp_wait() {
    asm volatile("cp.async.wait_group %0;" :: "n"(N));
}
__device__ __forceinline__ uint32_t lds_u32(uint32_t a) {
    uint32_t v; asm volatile("ld.shared.b32 %0, [%1];" : "=r"(v) : "r"(a)); return v;
}
__device__ __forceinline__ float lds_f32(uint32_t a) {
    float v; asm volatile("ld.shared.f32 %0, [%1];" : "=f"(v) : "r"(a)); return v;
}
__device__ __forceinline__ void sts_u32(uint32_t a, uint32_t v) {
    asm volatile("st.shared.b32 [%0], %1;" :: "r"(a), "r"(v));
}
__device__ __forceinline__ void sts_f32(uint32_t a, float v) {
    asm volatile("st.shared.f32 [%0], %1;" :: "r"(a), "f"(v));
}
__device__ __forceinline__ void sts_v2(uint32_t a, float x, float y) {
    asm volatile("st.shared.v2.f32 [%0], {%1, %2};" :: "r"(a), "f"(x), "f"(y));
}
#define LDSM4(r0, r1, r2, r3, addr) \
    asm volatile("ldmatrix.sync.aligned.m8n8.x4.shared.b16 {%0,%1,%2,%3}, [%4];" \
                 : "=r"(r0), "=r"(r1), "=r"(r2), "=r"(r3) : "r"(addr))

__device__ __forceinline__ void mma_bf16(float* d,
    uint32_t a0, uint32_t a1, uint32_t a2, uint32_t a3, uint32_t b0, uint32_t b1) {
    asm volatile("mma.sync.aligned.m16n8k16.row.col.f32.bf16.bf16.f32 "
                 "{%0,%1,%2,%3}, {%4,%5,%6,%7}, {%8,%9}, {%0,%1,%2,%3};"
                 : "+f"(d[0]), "+f"(d[1]), "+f"(d[2]), "+f"(d[3])
                 : "r"(a0), "r"(a1), "r"(a2), "r"(a3), "r"(b0), "r"(b1));
}

__global__ void init_kernel() {
    int i = blockIdx.x * blockDim.x + threadIdx.x;
    if (i < 2 * BB * HH) {
        ((__nv_bfloat16*)g_h0h)[i] = __float2bfloat16(0.0f);
        ((__nv_bfloat16*)g_h0l)[i] = __float2bfloat16(0.0f);
        ((__nv_bfloat16*)g_h1h)[i] = __float2bfloat16(0.0f);
        ((__nv_bfloat16*)g_h1l)[i] = __float2bfloat16(0.0f);
    }
    if (i == 0) { g_count = 0; g_gen = 0; }
}

// weight preconvert: permuted [u][tile][n][k], n = gate*16+j, k over [Wx|Wh]
__global__ void convert_weights_kernel(const float* __restrict__ Wx,
                                       const float* __restrict__ Wh) {
    size_t idx = (size_t)blockIdx.x * blockDim.x + threadIdx.x;
    if (idx >= 2ull * 64 * 64 * 2048) return;
    int k    = idx & 2047;
    int n    = (idx >> 11) & 63;
    int tile = (idx >> 17) & 63;
    int u    = (int)(idx >> 23);
    int gate = n >> 4, j = n & 15;
    int r = gate * 1024 + tile * 16 + j;
    float w = (k < 1024) ? Wx[((size_t)u * 4096 + r) * 1024 + k]
                         : Wh[((size_t)u * 4096 + r) * 1024 + (k - 1024)];
    __nv_bfloat16 hi = __float2bfloat16(w);
    __nv_bfloat16 lo = __float2bfloat16(w - __bfloat162float(hi));
    g_WBh[idx] = hi;
    g_WBl[idx] = lo;
}

__global__ void convert_embed_kernel(const float* __restrict__ embed) {
    int i = blockIdx.x * blockDim.x + threadIdx.x;
    if (i >= VV * DD) return;
    float w = embed[i];
    __nv_bfloat16 hi = __float2bfloat16(w);
    __nv_bfloat16 lo = __float2bfloat16(w - __bfloat162float(hi));
    g_embh[i] = hi;
    g_embl[i] = lo;
}

__device__ __forceinline__ void grid_barrier() {
    __syncthreads();
    if (threadIdx.x == 0) {
        unsigned gen = g_gen;
        __threadfence();
        if (atomicAdd(&g_count, 1u) == NCTA - 1) {
            g_count = 0;
            __threadfence();
            g_gen = gen + 1;
        } else {
            while (g_gen == gen) { __nanosleep(32); }
            __threadfence();
        }
    }
    __syncthreads();
}

// Persistent bf16-split mma.sync LSTM, k-split dual warp-groups.
// 128 CTAs x 512 thr (16 warps = 2 groups of 8). CTA: layer u = blockIdx>>6,
// tile = blockIdx&63. Group g computes chunks with parity g, warp tile m32n16.
// Phase: D[64 x 64] = A[64 x 2048] x W[64 x 2048]^T, 3-pass bf16 split.
__global__ __launch_bounds__(NTHR, 1) void lstm_persistent_kernel(
    const int* __restrict__ x, const float* __restrict__ bias)
{
    extern __shared__ char sm_raw[];
    const uint32_t sb = smem_u32(sm_raw);

    const int tid  = threadIdx.x;
    const int wid  = tid >> 5;
    const int lane = tid & 31;
    const int u    = blockIdx.x >> 6;
    const int tile = blockIdx.x & 63;
    const int col0 = tile * 16;

    const int grp = wid >> 3;         // k-parity group
    const int w8  = wid & 7;          // warp within group
    const int m0  = (w8 & 1) * 32;
    const int n0  = (w8 >> 1) * 16;
    const int lg  = lane >> 2;
    const int t2  = (lane & 3) * 2;

    // ldmatrix lane addresses (byte offsets within a staged array)
    const uint32_t a_lrow = (uint32_t)(m0 + (lane & 7) + ((lane >> 3) & 1) * 8) * PB
                          + ((lane >> 4) & 1) * 16;
    const uint32_t b_lrow = (uint32_t)(n0 + (lane & 7) + ((lane >> 4) & 1) * 8) * PB
                          + ((lane >> 3) & 1) * 16;

    // staging role: q = array (0 AH, 1 AL, 2 BH, 3 BL); 128 threads per array,
    // thread covers f4 = rr&7 at rows (rr>>3) + 8*i for i<4 ... rr in [0,127]
    const int q  = tid >> 7;
    const int rr = tid & 127;        // 16 rows x 8 f4 slots
    const int srow = rr >> 3;        // base row (0..15); rows srow + 16*i, i<4
    const int sf4  = rr & 7;

    // pointwise role
    const int pj  = tid & 15;
    const int pb0 = tid >> 4;        // 0..31
    const float* bL = bias + u * 4096;
    const float bi_ = bL[0    + col0 + pj];
    const float bf_ = bL[1024 + col0 + pj];
    const float bg_ = bL[2048 + col0 + pj];
    const float bo_ = bL[3072 + col0 + pj];

    for (int i = tid; i < 64 * 17; i += NTHR) sts_f32(sb + SCST + i * 4, 0.0f);
    __syncthreads();

    const __nv_bfloat16* wbh = g_WBh + ((size_t)(u * 64 + tile) * 64) * 2048;
    const __nv_bfloat16* wbl = g_WBl + ((size_t)(u * 64 + tile) * 64) * 2048;
    const __nv_bfloat16* wsel = (q == 2) ? wbh : wbl;   // used when q >= 2

    for (int p = 0; p <= TT; p++) {
        const bool valid = (u == 0) ? (p < TT) : (p >= 1);
        const int  tc    = (u == 0) ? (valid ? p : TT - 1) : (valid ? p - 1 : 0);
        const int  wbuf  = tc & 1;
        const int  rbuf  = (tc + 1) & 1;

        if (tid < BB) sts_u32(sb + STOKS + tid * 4, (uint32_t)x[tid * TT + tc]);
        __syncthreads();

        float acc[2][2][4];
#pragma unroll
        for (int a = 0; a < 2; a++)
#pragma unroll
            for (int b = 0; b < 2; b++)
#pragma unroll
                for (int e = 0; e < 4; e++) acc[a][b][e] = 0.0f;

        // stage one chunk c into smem chunk base `dstc`; 4 cp16 per thread
        auto stage_one = [&](int c, uint32_t dstc) {
            const uint32_t dstb = dstc + q * ARR + sf4 * 16;
#pragma unroll
            for (int i = 0; i < 4; i++) {
                const int row = srow + 16 * i;
                const uint32_t dst = dstb + (uint32_t)row * PB;
                const __nv_bfloat16* src;
                if (q >= 2) {
                    src = wsel + (size_t)row * 2048 + c * KC + sf4 * 8;
                } else {
                    if (u == 0) {
                        if (c < 16) {
                            int tok = (int)lds_u32(sb + STOKS + row * 4);
                            src = ((q == 0) ? g_embh : g_embl) + (size_t)tok * DD + c * KC + sf4 * 8;
                        } else {
                            src = ((q == 0) ? g_h0h[rbuf][row] : g_h0l[rbuf][row]) + (c - 16) * KC + sf4 * 8;
                        }
                    } else {
                        if (c < 16) src = ((q == 0) ? g_h0h[wbuf][row] : g_h0l[wbuf][row]) + c * KC + sf4 * 8;
                        else        src = ((q == 0) ? g_h1h[rbuf][row] : g_h1l[rbuf][row]) + (c - 16) * KC + sf4 * 8;
                    }
                }
                cp16(dst, src);
            }
        };
        // stage a chunk PAIR pp into ring slot pp%3; one commit group
        auto stage_pair = [&](int pp) {
            const uint32_t slotb = sb + (uint32_t)(pp % 3) * SLOT;
            stage_one(2 * pp,     slotb);
            stage_one(2 * pp + 1, slotb + CHUNK);
            cp_commit();
        };

        stage_pair(0); stage_pair(1);

        for (int pi = 0; pi < NPAIR; pi++) {
            if (pi < NPAIR - 1) cp_wait<1>(); else cp_wait<0>();
            __syncthreads();                     // pair pi ready; pair pi-1 compute done
            if (pi + 2 < NPAIR) stage_pair(pi + 2);  // overwrites slot of pair pi-1

            // my chunk within the pair
            const uint32_t cb = sb + (uint32_t)(pi % 3) * SLOT + (uint32_t)grp * CHUNK;
            const uint32_t aH  = cb + a_lrow;
            const uint32_t aL  = cb + ARR + a_lrow;
            const uint32_t bH  = cb + 2 * ARR + b_lrow;
            const uint32_t bLo = cb + 3 * ARR + b_lrow;
#pragma unroll
            for (int ks = 0; ks < 4; ks++) {
                const uint32_t ko = ks * 32;
                uint32_t ah[8], al[8], bh[4], bl[4];
                LDSM4(ah[0], ah[1], ah[2], ah[3], aH + ko);
                LDSM4(ah[4], ah[5], ah[6], ah[7], aH + ko + 16 * PB);
                LDSM4(bh[0], bh[1], bh[2], bh[3], bH + ko);
                LDSM4(al[0], al[1], al[2], al[3], aL + ko);
                LDSM4(al[4], al[5], al[6], al[7], aL + ko + 16 * PB);
                LDSM4(bl[0], bl[1], bl[2], bl[3], bLo + ko);
#pragma unroll
                for (int mi = 0; mi < 2; mi++) {
                    const uint32_t* A   = ah + mi * 4;
                    const uint32_t* AL2 = al + mi * 4;
#pragma unroll
                    for (int ni = 0; ni < 2; ni++) {
                        mma_bf16(acc[mi][ni], A[0], A[1], A[2], A[3], bh[2 * ni], bh[2 * ni + 1]);
                        mma_bf16(acc[mi][ni], A[0], A[1], A[2], A[3], bl[2 * ni], bl[2 * ni + 1]);
                        mma_bf16(acc[mi][ni], AL2[0], AL2[1], AL2[2], AL2[3], bh[2 * ni], bh[2 * ni + 1]);
                    }
                }
            }
        }
        __syncthreads();   // all compute done; stage buffers (and gate alias) free

        // group 0 writes partials, group 1 adds -> gate smem [64 m][68 f32 pitch]
        if (grp == 0) {
#pragma unroll
            for (int mi = 0; mi < 2; mi++) {
                const uint32_t grow = sb + SGATE + (uint32_t)(m0 + mi * 16 + lg) * 272
                                    + (uint32_t)(n0 + t2) * 4;
#pragma unroll
                for (int ni = 0; ni < 2; ni++) {
                    sts_v2(grow + ni * 32,           acc[mi][ni][0], acc[mi][ni][1]);
                    sts_v2(grow + ni * 32 + 8 * 272, acc[mi][ni][2], acc[mi][ni][3]);
                }
            }
        }
        __syncthreads();
        if (grp == 1) {
#pragma unroll
            for (int mi = 0; mi < 2; mi++) {
                const uint32_t grow = sb + SGATE + (uint32_t)(m0 + mi * 16 + lg) * 272
                                    + (uint32_t)(n0 + t2) * 4;
#pragma unroll
                for (int ni = 0; ni < 2; ni++) {
                    const uint32_t g0 = grow + ni * 32;
                    const uint32_t g1 = grow + ni * 32 + 8 * 272;
                    sts_v2(g0, lds_f32(g0) + acc[mi][ni][0], lds_f32(g0 + 4) + acc[mi][ni][1]);
                    sts_v2(g1, lds_f32(g1) + acc[mi][ni][2], lds_f32(g1 + 4) + acc[mi][ni][3]);
                }
            }
        }
        __syncthreads();

        // pointwise: thread owns col j = pj, batches pb0 and pb0+32
        if (valid) {
#pragma unroll
            for (int qq = 0; qq < 2; qq++) {
                const int b   = pb0 + 32 * qq;
                const int col = col0 + pj;
                const uint32_t gaddr = sb + SGATE + b * 272;
                float gi = lds_f32(gaddr + (0  + pj) * 4) + bi_;
                float gf = lds_f32(gaddr + (16 + pj) * 4) + bf_;
                float gg = lds_f32(gaddr + (32 + pj) * 4) + bg_;
                float go = lds_f32(gaddr + (48 + pj) * 4) + bo_;
                const uint32_t caddr = sb + SCST + (b * 17 + pj) * 4;
                float c_old = lds_f32(caddr);
                float c_new = sigf(gf) * c_old + sigf(gi) * tanhf(gg);
                float h_new = sigf(go) * tanhf(c_new);
                sts_f32(caddr, c_new);
                __nv_bfloat16 hh = __float2bfloat16(h_new);
                __nv_bfloat16 hl = __float2bfloat16(h_new - __bfloat162float(hh));
                if (u == 0) {
                    g_h0h[wbuf][b][col] = hh;
                    g_h0l[wbuf][b][col] = hl;
                } else {
                    g_h1h[wbuf][b][col] = hh;
                    g_h1l[wbuf][b][col] = hl;
                    g_Hout[((size_t)b * TT + tc) * HH + col] = h_new;
                }
            }
        }
        grid_barrier();
    }
}

// logits[m, v] = g_Hout[m, :] . Wout[v, :] + bout[v]  (M=32768, N=128, K=1024)
__global__ __launch_bounds__(128) void out_proj_kernel(
    const float* __restrict__ Wout, const float* __restrict__ bout,
    float* __restrict__ out)
{
    __shared__ float As[32][68];
    __shared__ float Ws[32][36];

    const int tid = threadIdx.x;
    const int m0  = blockIdx.x * 64;
    const int v0  = blockIdx.y * 32;
    const int tm  = tid & 15;
    const int tn  = tid >> 4;

    float acc[4][4];
#pragma unroll
    for (int i = 0; i < 4; i++)
#pragma unroll
        for (int j = 0; j < 4; j++) acc[i][j] = 0.0f;

#pragma unroll 1
    for (int k0 = 0; k0 < HH; k0 += 32) {
#pragma unroll
        for (int qy = 0; qy < 4; qy++) {
            int idx = tid + 128 * qy;
            int bb = idx >> 3, kv = idx & 7, k = k0 + kv * 4;
            float4 v = *reinterpret_cast<const float4*>(&g_Hout[(size_t)(m0 + bb) * HH + k]);
            int kr = kv * 4;
            As[kr + 0][bb] = v.x; As[kr + 1][bb] = v.y;
            As[kr + 2][bb] = v.z; As[kr + 3][bb] = v.w;
        }
#pragma unroll
        for (int qy = 0; qy < 2; qy++) {
            int idx = tid + 128 * qy;
            int n = idx >> 3, kv = idx & 7, k = k0 + kv * 4;
            float4 v = *reinterpret_cast<const float4*>(&Wout[(size_t)(v0 + n) * HH + k]);
            int kr = kv * 4;
            Ws[kr + 0][n] = v.x; Ws[kr + 1][n] = v.y;
            Ws[kr + 2][n] = v.z; Ws[kr + 3][n] = v.w;
        }
        __syncthreads();
#pragma unroll
        for (int kk = 0; kk < 32; kk++) {
            float4 a = *reinterpret_cast<const float4*>(&As[kk][tm << 2]);
            float4 w = *reinterpret_cast<const float4*>(&Ws[kk][tn << 2]);
            float av[4] = {a.x, a.y, a.z, a.w};
            float wv[4] = {w.x, w.y, w.z, w.w};
#pragma unroll
            for (int i = 0; i < 4; i++)
#pragma unroll
                for (int j = 0; j < 4; j++)
                    acc[i][j] = fmaf(av[i], wv[j], acc[i][j]);
        }
        __syncthreads();
    }

#pragma unroll
    for (int i = 0; i < 4; i++) {
        int m = m0 + (tm << 2) + i;
#pragma unroll
        for (int j = 0; j < 4; j++) {
            int v = v0 + (tn << 2) + j;
            out[(size_t)m * VV + v] = acc[i][j] + bout[v];
        }
    }
}

extern "C" void kernel_launch(void* const* d_in, const int* in_sizes, int n_in,
                              void* d_out, int out_size)
{
    const int*   x     = (const int*)d_in[0];
    const float* embed = (const float*)d_in[1];
    const float* Wx    = (const float*)d_in[2];
    const float* Wh    = (const float*)d_in[3];
    const float* bias  = (const float*)d_in[4];
    const float* Wout  = (const float*)d_in[5];
    const float* bout  = (const float*)d_in[6];
    float*       out   = (float*)d_out;

    static int smem_set = 0;
    if (!smem_set) {
        cudaFuncSetAttribute(lstm_persistent_kernel,
                             cudaFuncAttributeMaxDynamicSharedMemorySize, SMEM_DYN);
        smem_set = 1;
    }

    init_kernel<<<(2 * BB * HH + 255) / 256, 256>>>();
    convert_weights_kernel<<<(int)((2ull * 64 * 64 * 2048 + 255) / 256), 256>>>(Wx, Wh);
    convert_embed_kernel<<<(VV * DD + 255) / 256, 256>>>(embed);
    lstm_persistent_kernel<<<NCTA, NTHR, SMEM_DYN>>>(x, bias);
    out_proj_kernel<<<dim3(BB * TT / 64, VV / 32), 128>>>(Wout, bout, out);
}

// round 13
// speedup vs baseline: 2.3847x; 1.2907x over previous
#include <cuda_runtime.h>
#include <cuda_fp16.h>
#include <math.h>
#include <stdint.h>

#define BB 64
#define TT 512
#define DD 1024
#define HH 1024
#define VV 128
#define NCTA 128
#define NTHR 512
#define KC 64            // k elements per chunk
#define NCH 32           // chunks per phase (K = 2048)
#define NPAIR 16         // chunk pairs per phase
#define PB 144           // bytes per staged row (64 fp16 + 8 pad)

// ---- dynamic smem layout (byte offsets) ----
#define ARR    9216          // one staged array: 64 rows * 144B
#define CHUNK  (3 * ARR)     // A(act), WH, WL = 27648B per chunk
#define SLOT   (2 * CHUNK)   // ring slot = one chunk PAIR = 55296B
#define NSLOT  4
#define SGATE  0                         // f32 [64][68] (aliases slot 0; safe)
#define SCST   (NSLOT * SLOT)            // 221184: f32 [64][17] persistent
#define STOKS  (SCST + 64 * 17 * 4)      // 64 ints
#define SMEM_DYN (STOKS + 256 + 256)     // 226048

// ---- persistent device scratch ----
__device__ __half g_WFh[2ull * 64 * 64 * 2048];  // permuted weights hi (fp16)
__device__ __half g_WFl[2ull * 64 * 64 * 2048];  // permuted weights lo (fp16)
__device__ __half g_embf[VV * DD];
__device__ __half g_h0f[2][BB][HH];
__device__ __half g_h1f[2][BB][HH];
__device__ float g_Hout[(size_t)BB * TT * HH];
__device__ volatile unsigned g_gen;
__device__ unsigned g_count;

__device__ __forceinline__ float sigf(float v) { return 1.0f / (1.0f + expf(-v)); }

__device__ __forceinline__ uint32_t smem_u32(const void* p) {
    uint32_t a;
    asm("{ .reg .u64 t; cvta.to.shared.u64 t, %1; cvt.u32.u64 %0, t; }" : "=r"(a) : "l"(p));
    return a;
}
__device__ __forceinline__ void cp16(uint32_t dst, const void* src) {
    asm volatile("cp.async.cg.shared.global [%0], [%1], 16;" :: "r"(dst), "l"(src));
}
__device__ __forceinline__ void cp_commit() { asm volatile("cp.async.commit_group;"); }
template<int N> __device__ __forceinline__ void cp_wait() {
    asm volatile("cp.async.wait_group %0;" :: "n"(N));
}
__device__ __forceinline__ uint32_t lds_u32(uint32_t a) {
    uint32_t v; asm volatile("ld.shared.b32 %0, [%1];" : "=r"(v) : "r"(a)); return v;
}
__device__ __forceinline__ float lds_f32(uint32_t a) {
    float v; asm volatile("ld.shared.f32 %0, [%1];" : "=f"(v) : "r"(a)); return v;
}
__device__ __forceinline__ void sts_u32(uint32_t a, uint32_t v) {
    asm volatile("st.shared.b32 [%0], %1;" :: "r"(a), "r"(v));
}
__device__ __forceinline__ void sts_f32(uint32_t a, float v) {
    asm volatile("st.shared.f32 [%0], %1;" :: "r"(a), "f"(v));
}
__device__ __forceinline__ void sts_v2(uint32_t a, float x, float y) {
    asm volatile("st.shared.v2.f32 [%0], {%1, %2};" :: "r"(a), "f"(x), "f"(y));
}
#define LDSM4(r0, r1, r2, r3, addr) \
    asm volatile("ldmatrix.sync.aligned.m8n8.x4.shared.b16 {%0,%1,%2,%3}, [%4];" \
                 : "=r"(r0), "=r"(r1), "=r"(r2), "=r"(r3) : "r"(addr))

__device__ __forceinline__ void mma_f16(float* d,
    uint32_t a0, uint32_t a1, uint32_t a2, uint32_t a3, uint32_t b0, uint32_t b1) {
    asm volatile("mma.sync.aligned.m16n8k16.row.col.f32.f16.f16.f32 "
                 "{%0,%1,%2,%3}, {%4,%5,%6,%7}, {%8,%9}, {%0,%1,%2,%3};"
                 : "+f"(d[0]), "+f"(d[1]), "+f"(d[2]), "+f"(d[3])
                 : "r"(a0), "r"(a1), "r"(a2), "r"(a3), "r"(b0), "r"(b1));
}

__global__ void init_kernel() {
    int i = blockIdx.x * blockDim.x + threadIdx.x;
    if (i < 2 * BB * HH) {
        ((__half*)g_h0f)[i] = __float2half(0.0f);
        ((__half*)g_h1f)[i] = __float2half(0.0f);
    }
    if (i == 0) { g_count = 0; g_gen = 0; }
}

// weight preconvert: permuted [u][tile][n][k], n = gate*16+j, k over [Wx|Wh]
__global__ void convert_weights_kernel(const float* __restrict__ Wx,
                                       const float* __restrict__ Wh) {
    size_t idx = (size_t)blockIdx.x * blockDim.x + threadIdx.x;
    if (idx >= 2ull * 64 * 64 * 2048) return;
    int k    = idx & 2047;
    int n    = (idx >> 11) & 63;
    int tile = (idx >> 17) & 63;
    int u    = (int)(idx >> 23);
    int gate = n >> 4, j = n & 15;
    int r = gate * 1024 + tile * 16 + j;
    float w = (k < 1024) ? Wx[((size_t)u * 4096 + r) * 1024 + k]
                         : Wh[((size_t)u * 4096 + r) * 1024 + (k - 1024)];
    __half hi = __float2half(w);
    __half lo = __float2half(w - __half2float(hi));
    g_WFh[idx] = hi;
    g_WFl[idx] = lo;
}

__global__ void convert_embed_kernel(const float* __restrict__ embed) {
    int i = blockIdx.x * blockDim.x + threadIdx.x;
    if (i >= VV * DD) return;
    g_embf[i] = __float2half(embed[i]);
}

__device__ __forceinline__ void grid_barrier() {
    __syncthreads();
    if (threadIdx.x == 0) {
        unsigned gen = g_gen;
        __threadfence();
        if (atomicAdd(&g_count, 1u) == NCTA - 1) {
            g_count = 0;
            __threadfence();
            g_gen = gen + 1;
        } else {
            while (g_gen == gen) { __nanosleep(32); }
            __threadfence();
        }
    }
    __syncthreads();
}

// Persistent fp16 2-pass mma.sync LSTM, k-split dual warp-groups, 4-slot ring.
// 128 CTAs x 512 thr (16 warps = 2 groups of 8). CTA: layer u = blockIdx>>6,
// tile = blockIdx&63. Group g computes chunks with parity g, warp tile m32n16.
// Phase: D[64 x 64] = A[64 x 2048] x (Wh + Wl)[64 x 2048]^T  (A single fp16).
__global__ __launch_bounds__(NTHR, 1) void lstm_persistent_kernel(
    const int* __restrict__ x, const float* __restrict__ bias)
{
    extern __shared__ char sm_raw[];
    const uint32_t sb = smem_u32(sm_raw);

    const int tid  = threadIdx.x;
    const int wid  = tid >> 5;
    const int lane = tid & 31;
    const int u    = blockIdx.x >> 6;
    const int tile = blockIdx.x & 63;
    const int col0 = tile * 16;

    const int grp = wid >> 3;         // k-parity group
    const int w8  = wid & 7;          // warp within group
    const int m0  = (w8 & 1) * 32;
    const int n0  = (w8 >> 1) * 16;
    const int lg  = lane >> 2;
    const int t2  = (lane & 3) * 2;

    // ldmatrix lane addresses (byte offsets within a staged array)
    const uint32_t a_lrow = (uint32_t)(m0 + (lane & 7) + ((lane >> 3) & 1) * 8) * PB
                          + ((lane >> 4) & 1) * 16;
    const uint32_t b_lrow = (uint32_t)(n0 + (lane & 7) + ((lane >> 4) & 1) * 8) * PB
                          + ((lane >> 3) & 1) * 16;

    // pointwise role
    const int pj  = tid & 15;
    const int pb0 = tid >> 4;        // 0..31
    const float* bL = bias + u * 4096;
    const float bi_ = bL[0    + col0 + pj];
    const float bf_ = bL[1024 + col0 + pj];
    const float bg_ = bL[2048 + col0 + pj];
    const float bo_ = bL[3072 + col0 + pj];

    for (int i = tid; i < 64 * 17; i += NTHR) sts_f32(sb + SCST + i * 4, 0.0f);
    __syncthreads();

    const __half* wfh = g_WFh + ((size_t)(u * 64 + tile) * 64) * 2048;
    const __half* wfl = g_WFl + ((size_t)(u * 64 + tile) * 64) * 2048;

    for (int p = 0; p <= TT; p++) {
        const bool valid = (u == 0) ? (p < TT) : (p >= 1);
        const int  tc    = (u == 0) ? (valid ? p : TT - 1) : (valid ? p - 1 : 0);
        const int  wbuf  = tc & 1;
        const int  rbuf  = (tc + 1) & 1;

        if (tid < BB) sts_u32(sb + STOKS + tid * 4, (uint32_t)x[tid * TT + tc]);
        __syncthreads();

        float acc[2][2][4];
#pragma unroll
        for (int a = 0; a < 2; a++)
#pragma unroll
            for (int b = 0; b < 2; b++)
#pragma unroll
                for (int e = 0; e < 4; e++) acc[a][b][e] = 0.0f;

        // stage one chunk c (3 arrays x 64 rows x 8 f4 = 1536 cp16; 3 per thread)
        auto stage_one = [&](int c, uint32_t dstc) {
#pragma unroll
            for (int i = 0; i < 3; i++) {
                const int slot = tid + NTHR * i;      // 0..1535
                const int arr  = slot >> 9;           // 0 A, 1 WH, 2 WL
                const int rr   = slot & 511;
                const int row  = rr >> 3;
                const int f4   = rr & 7;
                const uint32_t dst = dstc + (uint32_t)arr * ARR + (uint32_t)row * PB + f4 * 16;
                const __half* src;
                if (arr == 1) {
                    src = wfh + (size_t)row * 2048 + c * KC + f4 * 8;
                } else if (arr == 2) {
                    src = wfl + (size_t)row * 2048 + c * KC + f4 * 8;
                } else {
                    if (u == 0) {
                        if (c < 16) {
                            int tok = (int)lds_u32(sb + STOKS + row * 4);
                            src = g_embf + (size_t)tok * DD + c * KC + f4 * 8;
                        } else {
                            src = g_h0f[rbuf][row] + (c - 16) * KC + f4 * 8;
                        }
                    } else {
                        if (c < 16) src = g_h0f[wbuf][row] + c * KC + f4 * 8;
                        else        src = g_h1f[rbuf][row] + (c - 16) * KC + f4 * 8;
                    }
                }
                cp16(dst, src);
            }
        };
        // stage a chunk PAIR pp into ring slot pp%4; one commit group
        auto stage_pair = [&](int pp) {
            const uint32_t slotb = sb + (uint32_t)(pp & 3) * SLOT;
            stage_one(2 * pp,     slotb);
            stage_one(2 * pp + 1, slotb + CHUNK);
            cp_commit();
        };

        stage_pair(0); stage_pair(1); stage_pair(2);

        for (int pi = 0; pi < NPAIR; pi++) {
            if (pi < NPAIR - 2)      cp_wait<2>();
            else if (pi == NPAIR - 2) cp_wait<1>();
            else                      cp_wait<0>();
            __syncthreads();                     // pair pi ready; pair pi-1 compute done
            if (pi + 3 < NPAIR) stage_pair(pi + 3);  // overwrites slot of pair pi-1

            // my chunk within the pair
            const uint32_t cb = sb + (uint32_t)(pi & 3) * SLOT + (uint32_t)grp * CHUNK;
            const uint32_t aA  = cb + a_lrow;
            const uint32_t bH  = cb + ARR + b_lrow;
            const uint32_t bLo = cb + 2 * ARR + b_lrow;
#pragma unroll
            for (int ks = 0; ks < 4; ks++) {
                const uint32_t ko = ks * 32;
                uint32_t a[8], bh[4], bl[4];
                LDSM4(a[0], a[1], a[2], a[3], aA + ko);
                LDSM4(a[4], a[5], a[6], a[7], aA + ko + 16 * PB);
                LDSM4(bh[0], bh[1], bh[2], bh[3], bH + ko);
                LDSM4(bl[0], bl[1], bl[2], bl[3], bLo + ko);
#pragma unroll
                for (int mi = 0; mi < 2; mi++) {
                    const uint32_t* A = a + mi * 4;
#pragma unroll
                    for (int ni = 0; ni < 2; ni++) {
                        mma_f16(acc[mi][ni], A[0], A[1], A[2], A[3], bh[2 * ni], bh[2 * ni + 1]);
                        mma_f16(acc[mi][ni], A[0], A[1], A[2], A[3], bl[2 * ni], bl[2 * ni + 1]);
                    }
                }
            }
        }
        __syncthreads();   // all compute done; stage buffers (and gate alias) free

        // group 0 writes partials, group 1 adds -> gate smem [64 m][68 f32 pitch]
        if (grp == 0) {
#pragma unroll
            for (int mi = 0; mi < 2; mi++) {
                const uint32_t grow = sb + SGATE + (uint32_t)(m0 + mi * 16 + lg) * 272
                                    + (uint32_t)(n0 + t2) * 4;
#pragma unroll
                for (int ni = 0; ni < 2; ni++) {
                    sts_v2(grow + ni * 32,           acc[mi][ni][0], acc[mi][ni][1]);
                    sts_v2(grow + ni * 32 + 8 * 272, acc[mi][ni][2], acc[mi][ni][3]);
                }
            }
        }
        __syncthreads();
        if (grp == 1) {
#pragma unroll
            for (int mi = 0; mi < 2; mi++) {
                const uint32_t grow = sb + SGATE + (uint32_t)(m0 + mi * 16 + lg) * 272
                                    + (uint32_t)(n0 + t2) * 4;
#pragma unroll
                for (int ni = 0; ni < 2; ni++) {
                    const uint32_t g0 = grow + ni * 32;
                    const uint32_t g1 = grow + ni * 32 + 8 * 272;
                    sts_v2(g0, lds_f32(g0) + acc[mi][ni][0], lds_f32(g0 + 4) + acc[mi][ni][1]);
                    sts_v2(g1, lds_f32(g1) + acc[mi][ni][2], lds_f32(g1 + 4) + acc[mi][ni][3]);
                }
            }
        }
        __syncthreads();

        // pointwise: thread owns col j = pj, batches pb0 and pb0+32
        if (valid) {
#pragma unroll
            for (int qq = 0; qq < 2; qq++) {
                const int b   = pb0 + 32 * qq;
                const int col = col0 + pj;
                const uint32_t gaddr = sb + SGATE + b * 272;
                float gi = lds_f32(gaddr + (0  + pj) * 4) + bi_;
                float gf = lds_f32(gaddr + (16 + pj) * 4) + bf_;
                float gg = lds_f32(gaddr + (32 + pj) * 4) + bg_;
                float go = lds_f32(gaddr + (48 + pj) * 4) + bo_;
                const uint32_t caddr = sb + SCST + (b * 17 + pj) * 4;
                float c_old = lds_f32(caddr);
                float c_new = sigf(gf) * c_old + sigf(gi) * tanhf(gg);
                float h_new = sigf(go) * tanhf(c_new);
                sts_f32(caddr, c_new);
                if (u == 0) {
                    g_h0f[wbuf][b][col] = __float2half(h_new);
                } else {
                    g_h1f[wbuf][b][col] = __float2half(h_new);
                    g_Hout[((size_t)b * TT + tc) * HH + col] = h_new;
                }
            }
        }
        grid_barrier();
    }
}

// logits[m, v] = g_Hout[m, :] . Wout[v, :] + bout[v]  (M=32768, N=128, K=1024)
__global__ __launch_bounds__(128) void out_proj_kernel(
    const float* __restrict__ Wout, const float* __restrict__ bout,
    float* __restrict__ out)
{
    __shared__ float As[32][68];
    __shared__ float Ws[32][36];

    const int tid = threadIdx.x;
    const int m0  = blockIdx.x * 64;
    const int v0  = blockIdx.y * 32;
    const int tm  = tid & 15;
    const int tn  = tid >> 4;

    float acc[4][4];
#pragma unroll
    for (int i = 0; i < 4; i++)
#pragma unroll
        for (int j = 0; j < 4; j++) acc[i][j] = 0.0f;

#pragma unroll 1
    for (int k0 = 0; k0 < HH; k0 += 32) {
#pragma unroll
        for (int qy = 0; qy < 4; qy++) {
            int idx = tid + 128 * qy;
            int bb = idx >> 3, kv = idx & 7, k = k0 + kv * 4;
            float4 v = *reinterpret_cast<const float4*>(&g_Hout[(size_t)(m0 + bb) * HH + k]);
            int kr = kv * 4;
            As[kr + 0][bb] = v.x; As[kr + 1][bb] = v.y;
            As[kr + 2][bb] = v.z; As[kr + 3][bb] = v.w;
        }
#pragma unroll
        for (int qy = 0; qy < 2; qy++) {
            int idx = tid + 128 * qy;
            int n = idx >> 3, kv = idx & 7, k = k0 + kv * 4;
            float4 v = *reinterpret_cast<const float4*>(&Wout[(size_t)(v0 + n) * HH + k]);
            int kr = kv * 4;
            Ws[kr + 0][n] = v.x; Ws[kr + 1][n] = v.y;
            Ws[kr + 2][n] = v.z; Ws[kr + 3][n] = v.w;
        }
        __syncthreads();
#pragma unroll
        for (int kk = 0; kk < 32; kk++) {
            float4 a = *reinterpret_cast<const float4*>(&As[kk][tm << 2]);
            float4 w = *reinterpret_cast<const float4*>(&Ws[kk][tn << 2]);
            float av[4] = {a.x, a.y, a.z, a.w};
            float wv[4] = {w.x, w.y, w.z, w.w};
#pragma unroll
            for (int i = 0; i < 4; i++)
#pragma unroll
                for (int j = 0; j < 4; j++)
                    acc[i][j] = fmaf(av[i], wv[j], acc[i][j]);
        }
        __syncthreads();
    }

#pragma unroll
    for (int i = 0; i < 4; i++) {
        int m = m0 + (tm << 2) + i;
#pragma unroll
        for (int j = 0; j < 4; j++) {
            int v = v0 + (tn << 2) + j;
            out[(size_t)m * VV + v] = acc[i][j] + bout[v];
        }
    }
}

extern "C" void kernel_launch(void* const* d_in, const int* in_sizes, int n_in,
                              void* d_out, int out_size)
{
    const int*   x     = (const int*)d_in[0];
    const float* embed = (const float*)d_in[1];
    const float* Wx    = (const float*)d_in[2];
    const float* Wh    = (const float*)d_in[3];
    const float* bias  = (const float*)d_in[4];
    const float* Wout  = (const float*)d_in[5];
    const float* bout  = (const float*)d_in[6];
    float*       out   = (float*)d_out;

    static int smem_set = 0;
    if (!smem_set) {
        cudaFuncSetAttribute(lstm_persistent_kernel,
                             cudaFuncAttributeMaxDynamicSharedMemorySize, SMEM_DYN);
        smem_set = 1;
    }

    init_kernel<<<(2 * BB * HH + 255) / 256, 256>>>();
    convert_weights_kernel<<<(int)((2ull * 64 * 64 * 2048 + 255) / 256), 256>>>(Wx, Wh);
    convert_embed_kernel<<<(VV * DD + 255) / 256, 256>>>(embed);
    lstm_persistent_kernel<<<NCTA, NTHR, SMEM_DYN>>>(x, bias);
    out_proj_kernel<<<dim3(BB * TT / 64, VV / 32), 128>>>(Wout, bout, out);
}

// round 14
// speedup vs baseline: 3.7302x; 1.5643x over previous
#include <cuda_runtime.h>
#include <cuda_fp16.h>
#include <math.h>
#include <stdint.h>

#define BB 64
#define TT 512
#define DD 1024
#define HH 1024
#define VV 128
#define NCTA 128
#define NTHR 512
#define KC 64            // k elements per chunk
#define NCHG 16          // chunks per group per phase (each group owns K/2 = 1024)
#define PB 144           // bytes per staged row (64 fp16 + 8 pad)

// ---- dynamic smem layout (byte offsets) ----
#define ARR    9216            // one staged array: 64 rows * 144B
#define CHUNK  (2 * ARR)       // A(act), W = 18432B per chunk
#define GRING  (4 * CHUNK)     // per-group ring: 4 slots = 73728B
#define SGATE  0               // f32 [64][68] (aliases ring area; used post-sync)
#define SCST   (2 * GRING)     // 147456: f32 [64][17] persistent
#define STOKS  (SCST + 64 * 17 * 4)
#define SMEM_DYN (STOKS + 256 + 256)

// ---- persistent device scratch ----
__device__ __half g_WF[2ull * 64 * 64 * 2048];   // permuted weights (fp16)
__device__ __half g_embf[VV * DD];
__device__ __half g_h0f[2][BB][HH];
__device__ __half g_h1f[2][BB][HH];
__device__ float g_Hout[(size_t)BB * TT * HH];
__device__ volatile unsigned g_gen;
__device__ unsigned g_count;

__device__ __forceinline__ float sigf(float v) { return 1.0f / (1.0f + expf(-v)); }

__device__ __forceinline__ uint32_t smem_u32(const void* p) {
    uint32_t a;
    asm("{ .reg .u64 t; cvta.to.shared.u64 t, %1; cvt.u32.u64 %0, t; }" : "=r"(a) : "l"(p));
    return a;
}
__device__ __forceinline__ void cp16(uint32_t dst, const void* src) {
    asm volatile("cp.async.cg.shared.global [%0], [%1], 16;" :: "r"(dst), "l"(src));
}
__device__ __forceinline__ void cp_commit() { asm volatile("cp.async.commit_group;"); }
template<int N> __device__ __forceinline__ void cp_wait() {
    asm volatile("cp.async.wait_group %0;" :: "n"(N));
}
__device__ __forceinline__ void bar_grp(int id) {
    asm volatile("bar.sync %0, 256;" :: "r"(id) : "memory");
}
__device__ __forceinline__ uint32_t lds_u32(uint32_t a) {
    uint32_t v; asm volatile("ld.shared.b32 %0, [%1];" : "=r"(v) : "r"(a)); return v;
}
__device__ __forceinline__ float lds_f32(uint32_t a) {
    float v; asm volatile("ld.shared.f32 %0, [%1];" : "=f"(v) : "r"(a)); return v;
}
__device__ __forceinline__ void sts_u32(uint32_t a, uint32_t v) {
    asm volatile("st.shared.b32 [%0], %1;" :: "r"(a), "r"(v));
}
__device__ __forceinline__ void sts_f32(uint32_t a, float v) {
    asm volatile("st.shared.f32 [%0], %1;" :: "r"(a), "f"(v));
}
__device__ __forceinline__ void sts_v2(uint32_t a, float x, float y) {
    asm volatile("st.shared.v2.f32 [%0], {%1, %2};" :: "r"(a), "f"(x), "f"(y));
}
#define LDSM4(r0, r1, r2, r3, addr) \
    asm volatile("ldmatrix.sync.aligned.m8n8.x4.shared.b16 {%0,%1,%2,%3}, [%4];" \
                 : "=r"(r0), "=r"(r1), "=r"(r2), "=r"(r3) : "r"(addr))

__device__ __forceinline__ void mma_f16(float* d,
    uint32_t a0, uint32_t a1, uint32_t a2, uint32_t a3, uint32_t b0, uint32_t b1) {
    asm volatile("mma.sync.aligned.m16n8k16.row.col.f32.f16.f16.f32 "
                 "{%0,%1,%2,%3}, {%4,%5,%6,%7}, {%8,%9}, {%0,%1,%2,%3};"
                 : "+f"(d[0]), "+f"(d[1]), "+f"(d[2]), "+f"(d[3])
                 : "r"(a0), "r"(a1), "r"(a2), "r"(a3), "r"(b0), "r"(b1));
}

__global__ void init_kernel() {
    int i = blockIdx.x * blockDim.x + threadIdx.x;
    if (i < 2 * BB * HH) {
        ((__half*)g_h0f)[i] = __float2half(0.0f);
        ((__half*)g_h1f)[i] = __float2half(0.0f);
    }
    if (i == 0) { g_count = 0; g_gen = 0; }
}

// weight preconvert: permuted [u][tile][n][k], n = gate*16+j, k over [Wx|Wh]
__global__ void convert_weights_kernel(const float* __restrict__ Wx,
                                       const float* __restrict__ Wh) {
    size_t idx = (size_t)blockIdx.x * blockDim.x + threadIdx.x;
    if (idx >= 2ull * 64 * 64 * 2048) return;
    int k    = idx & 2047;
    int n    = (idx >> 11) & 63;
    int tile = (idx >> 17) & 63;
    int u    = (int)(idx >> 23);
    int gate = n >> 4, j = n & 15;
    int r = gate * 1024 + tile * 16 + j;
    float w = (k < 1024) ? Wx[((size_t)u * 4096 + r) * 1024 + k]
                         : Wh[((size_t)u * 4096 + r) * 1024 + (k - 1024)];
    g_WF[idx] = __float2half(w);
}

__global__ void convert_embed_kernel(const float* __restrict__ embed) {
    int i = blockIdx.x * blockDim.x + threadIdx.x;
    if (i >= VV * DD) return;
    g_embf[i] = __float2half(embed[i]);
}

__device__ __forceinline__ void grid_barrier() {
    __syncthreads();
    if (threadIdx.x == 0) {
        unsigned gen = g_gen;
        __threadfence();
        if (atomicAdd(&g_count, 1u) == NCTA - 1) {
            g_count = 0;
            __threadfence();
            g_gen = gen + 1;
        } else {
            while (g_gen == gen) { __nanosleep(32); }
            __threadfence();
        }
    }
    __syncthreads();
}

// Persistent single-pass fp16 mma.sync LSTM, decoupled dual warp-groups.
// 128 CTAs x 512 thr (2 groups of 8 warps). CTA: layer u = blockIdx>>6,
// tile = blockIdx&63. Group g owns contiguous K half [g*1024, (g+1)*1024):
// stages its own chunks into its own 4-slot ring, syncs only group-locally
// (bar.sync 1+g, 256). Warp tile m32n16 over the 64x64 (batch x gate-col) tile.
__global__ __launch_bounds__(NTHR, 1) void lstm_persistent_kernel(
    const int* __restrict__ x, const float* __restrict__ bias)
{
    extern __shared__ char sm_raw[];
    const uint32_t sb = smem_u32(sm_raw);

    const int tid  = threadIdx.x;
    const int wid  = tid >> 5;
    const int lane = tid & 31;
    const int u    = blockIdx.x >> 6;
    const int tile = blockIdx.x & 63;
    const int col0 = tile * 16;

    const int grp = tid >> 8;         // warp-group (k half)
    const int gt  = tid & 255;        // thread within group
    const int w8  = wid & 7;          // warp within group
    const int m0  = (w8 & 1) * 32;
    const int n0  = (w8 >> 1) * 16;
    const int lg  = lane >> 2;
    const int t2  = (lane & 3) * 2;
    const int bar_id = 1 + grp;

    // ldmatrix lane addresses (byte offsets within a staged array)
    const uint32_t a_lrow = (uint32_t)(m0 + (lane & 7) + ((lane >> 3) & 1) * 8) * PB
                          + ((lane >> 4) & 1) * 16;
    const uint32_t b_lrow = (uint32_t)(n0 + (lane & 7) + ((lane >> 4) & 1) * 8) * PB
                          + ((lane >> 3) & 1) * 16;

    // pointwise role
    const int pj  = tid & 15;
    const int pb0 = tid >> 4;        // 0..31
    const float* bL = bias + u * 4096;
    const float bi_ = bL[0    + col0 + pj];
    const float bf_ = bL[1024 + col0 + pj];
    const float bg_ = bL[2048 + col0 + pj];
    const float bo_ = bL[3072 + col0 + pj];

    for (int i = tid; i < 64 * 17; i += NTHR) sts_f32(sb + SCST + i * 4, 0.0f);
    __syncthreads();

    // group g's weight half starts at k = g*1024
    const __half* wfg = g_WF + ((size_t)(u * 64 + tile) * 64) * 2048 + grp * 1024;
    const uint32_t ringb = sb + (uint32_t)grp * GRING;

    for (int p = 0; p <= TT; p++) {
        const bool valid = (u == 0) ? (p < TT) : (p >= 1);
        const int  tc    = (u == 0) ? (valid ? p : TT - 1) : (valid ? p - 1 : 0);
        const int  wbuf  = tc & 1;
        const int  rbuf  = (tc + 1) & 1;

        if (tid < BB) sts_u32(sb + STOKS + tid * 4, (uint32_t)x[tid * TT + tc]);
        __syncthreads();

        float acc[2][2][4];
#pragma unroll
        for (int a = 0; a < 2; a++)
#pragma unroll
            for (int b = 0; b < 2; b++)
#pragma unroll
                for (int e = 0; e < 4; e++) acc[a][b][e] = 0.0f;

        // stage group-local chunk ci (k = grp*1024 + ci*64): 1024 cp16 / 256 thr = 4 each
        auto stage_chunk = [&](int ci) {
            const uint32_t dstc = ringb + (uint32_t)(ci & 3) * CHUNK;
#pragma unroll
            for (int i = 0; i < 4; i++) {
                const int slot = gt + 256 * i;        // 0..1023
                const int arr  = slot >> 9;           // 0 A, 1 W
                const int rr   = slot & 511;
                const int row  = rr >> 3;
                const int f4   = rr & 7;
                const uint32_t dst = dstc + (uint32_t)arr * ARR + (uint32_t)row * PB + f4 * 16;
                const __half* src;
                if (arr == 1) {
                    src = wfg + (size_t)row * 2048 + ci * KC + f4 * 8;
                } else {
                    if (u == 0) {
                        if (grp == 0) {
                            int tok = (int)lds_u32(sb + STOKS + row * 4);
                            src = g_embf + (size_t)tok * DD + ci * KC + f4 * 8;
                        } else {
                            src = g_h0f[rbuf][row] + ci * KC + f4 * 8;
                        }
                    } else {
                        if (grp == 0) src = g_h0f[wbuf][row] + ci * KC + f4 * 8;
                        else          src = g_h1f[rbuf][row] + ci * KC + f4 * 8;
                    }
                }
                cp16(dst, src);
            }
            cp_commit();
        };

        // prologue: 3 chunks in flight (group-local)
        stage_chunk(0); stage_chunk(1); stage_chunk(2);

        for (int ci = 0; ci < NCHG; ci++) {
            if (ci < NCHG - 2)       cp_wait<2>();
            else if (ci == NCHG - 2) cp_wait<1>();
            else                     cp_wait<0>();
            bar_grp(bar_id);                      // chunk ci ready; compute(ci-1) done
            if (ci + 3 < NCHG) stage_chunk(ci + 3);  // overwrites slot (ci-1)&3 — safe

            const uint32_t cb = ringb + (uint32_t)(ci & 3) * CHUNK;
            const uint32_t aA = cb + a_lrow;
            const uint32_t bW = cb + ARR + b_lrow;
#pragma unroll
            for (int ks = 0; ks < 4; ks++) {
                const uint32_t ko = ks * 32;
                uint32_t a[8], b[4];
                LDSM4(a[0], a[1], a[2], a[3], aA + ko);
                LDSM4(a[4], a[5], a[6], a[7], aA + ko + 16 * PB);
                LDSM4(b[0], b[1], b[2], b[3], bW + ko);
#pragma unroll
                for (int mi = 0; mi < 2; mi++) {
                    const uint32_t* A = a + mi * 4;
#pragma unroll
                    for (int ni = 0; ni < 2; ni++)
                        mma_f16(acc[mi][ni], A[0], A[1], A[2], A[3], b[2 * ni], b[2 * ni + 1]);
                }
            }
        }
        __syncthreads();   // both groups done; ring area (and gate alias) free

        // group 0 writes partials, group 1 adds -> gate smem [64 m][68 f32 pitch]
        if (grp == 0) {
#pragma unroll
            for (int mi = 0; mi < 2; mi++) {
                const uint32_t grow = sb + SGATE + (uint32_t)(m0 + mi * 16 + lg) * 272
                                    + (uint32_t)(n0 + t2) * 4;
#pragma unroll
                for (int ni = 0; ni < 2; ni++) {
                    sts_v2(grow + ni * 32,           acc[mi][ni][0], acc[mi][ni][1]);
                    sts_v2(grow + ni * 32 + 8 * 272, acc[mi][ni][2], acc[mi][ni][3]);
                }
            }
        }
        __syncthreads();
        if (grp == 1) {
#pragma unroll
            for (int mi = 0; mi < 2; mi++) {
                const uint32_t grow = sb + SGATE + (uint32_t)(m0 + mi * 16 + lg) * 272
                                    + (uint32_t)(n0 + t2) * 4;
#pragma unroll
                for (int ni = 0; ni < 2; ni++) {
                    const uint32_t g0 = grow + ni * 32;
                    const uint32_t g1 = grow + ni * 32 + 8 * 272;
                    sts_v2(g0, lds_f32(g0) + acc[mi][ni][0], lds_f32(g0 + 4) + acc[mi][ni][1]);
                    sts_v2(g1, lds_f32(g1) + acc[mi][ni][2], lds_f32(g1 + 4) + acc[mi][ni][3]);
                }
            }
        }
        __syncthreads();

        // pointwise: thread owns col j = pj, batches pb0 and pb0+32
        if (valid) {
#pragma unroll
            for (int qq = 0; qq < 2; qq++) {
                const int b   = pb0 + 32 * qq;
                const int col = col0 + pj;
                const uint32_t gaddr = sb + SGATE + b * 272;
                float gi = lds_f32(gaddr + (0  + pj) * 4) + bi_;
                float gf = lds_f32(gaddr + (16 + pj) * 4) + bf_;
                float gg = lds_f32(gaddr + (32 + pj) * 4) + bg_;
                float go = lds_f32(gaddr + (48 + pj) * 4) + bo_;
                const uint32_t caddr = sb + SCST + (b * 17 + pj) * 4;
                float c_old = lds_f32(caddr);
                float c_new = sigf(gf) * c_old + sigf(gi) * tanhf(gg);
                float h_new = sigf(go) * tanhf(c_new);
                sts_f32(caddr, c_new);
                if (u == 0) {
                    g_h0f[wbuf][b][col] = __float2half(h_new);
                } else {
                    g_h1f[wbuf][b][col] = __float2half(h_new);
                    g_Hout[((size_t)b * TT + tc) * HH + col] = h_new;
                }
            }
        }
        grid_barrier();
    }
}

// logits[m, v] = g_Hout[m, :] . Wout[v, :] + bout[v]  (M=32768, N=128, K=1024)
__global__ __launch_bounds__(128) void out_proj_kernel(
    const float* __restrict__ Wout, const float* __restrict__ bout,
    float* __restrict__ out)
{
    __shared__ float As[32][68];
    __shared__ float Ws[32][36];

    const int tid = threadIdx.x;
    const int m0  = blockIdx.x * 64;
    const int v0  = blockIdx.y * 32;
    const int tm  = tid & 15;
    const int tn  = tid >> 4;

    float acc[4][4];
#pragma unroll
    for (int i = 0; i < 4; i++)
#pragma unroll
        for (int j = 0; j < 4; j++) acc[i][j] = 0.0f;

#pragma unroll 1
    for (int k0 = 0; k0 < HH; k0 += 32) {
#pragma unroll
        for (int qy = 0; qy < 4; qy++) {
            int idx = tid + 128 * qy;
            int bb = idx >> 3, kv = idx & 7, k = k0 + kv * 4;
            float4 v = *reinterpret_cast<const float4*>(&g_Hout[(size_t)(m0 + bb) * HH + k]);
            int kr = kv * 4;
            As[kr + 0][bb] = v.x; As[kr + 1][bb] = v.y;
            As[kr + 2][bb] = v.z; As[kr + 3][bb] = v.w;
        }
#pragma unroll
        for (int qy = 0; qy < 2; qy++) {
            int idx = tid + 128 * qy;
            int n = idx >> 3, kv = idx & 7, k = k0 + kv * 4;
            float4 v = *reinterpret_cast<const float4*>(&Wout[(size_t)(v0 + n) * HH + k]);
            int kr = kv * 4;
            Ws[kr + 0][n] = v.x; Ws[kr + 1][n] = v.y;
            Ws[kr + 2][n] = v.z; Ws[kr + 3][n] = v.w;
        }
        __syncthreads();
#pragma unroll
        for (int kk = 0; kk < 32; kk++) {
            float4 a = *reinterpret_cast<const float4*>(&As[kk][tm << 2]);
            float4 w = *reinterpret_cast<const float4*>(&Ws[kk][tn << 2]);
            float av[4] = {a.x, a.y, a.z, a.w};
            float wv[4] = {w.x, w.y, w.z, w.w};
#pragma unroll
            for (int i = 0; i < 4; i++)
#pragma unroll
                for (int j = 0; j < 4; j++)
                    acc[i][j] = fmaf(av[i], wv[j], acc[i][j]);
        }
        __syncthreads();
    }

#pragma unroll
    for (int i = 0; i < 4; i++) {
        int m = m0 + (tm << 2) + i;
#pragma unroll
        for (int j = 0; j < 4; j++) {
            int v = v0 + (tn << 2) + j;
            out[(size_t)m * VV + v] = acc[i][j] + bout[v];
        }
    }
}

extern "C" void kernel_launch(void* const* d_in, const int* in_sizes, int n_in,
                              void* d_out, int out_size)
{
    const int*   x     = (const int*)d_in[0];
    const float* embed = (const float*)d_in[1];
    const float* Wx    = (const float*)d_in[2];
    const float* Wh    = (const float*)d_in[3];
    const float* bias  = (const float*)d_in[4];
    const float* Wout  = (const float*)d_in[5];
    const float* bout  = (const float*)d_in[6];
    float*       out   = (float*)d_out;

    static int smem_set = 0;
    if (!smem_set) {
        cudaFuncSetAttribute(lstm_persistent_kernel,
                             cudaFuncAttributeMaxDynamicSharedMemorySize, SMEM_DYN);
        smem_set = 1;
    }

    init_kernel<<<(2 * BB * HH + 255) / 256, 256>>>();
    convert_weights_kernel<<<(int)((2ull * 64 * 64 * 2048 + 255) / 256), 256>>>(Wx, Wh);
    convert_embed_kernel<<<(VV * DD + 255) / 256, 256>>>(embed);
    lstm_persistent_kernel<<<NCTA, NTHR, SMEM_DYN>>>(x, bias);
    out_proj_kernel<<<dim3(BB * TT / 64, VV / 32), 128>>>(Wout, bout, out);
}